// round 1
// baseline (speedup 1.0000x reference)
#include <cuda_runtime.h>
#include <cstdint>
#include <math.h>

// Problem shape (fixed for this dataset entry)
#define NB   32
#define SEQ  2048
#define HD   64

#define BM 64          // Q rows per CTA
#define BN 64          // keys per tile
#define LDK 68         // stride (floats) for K / Q-stage / P smem  (conflict-free for B/A frag pattern)
#define LDV 72         // stride (floats) for V smem                 (conflict-free for PV B frag pattern)

__device__ __forceinline__ uint32_t f2tf32(float f) {
    uint32_t u;
    asm("cvt.rna.tf32.f32 %0, %1;" : "=r"(u) : "f"(f));
    return u;
}

__device__ __forceinline__ void mma_tf32(float& c0, float& c1, float& c2, float& c3,
                                         uint32_t a0, uint32_t a1, uint32_t a2, uint32_t a3,
                                         uint32_t b0, uint32_t b1) {
    asm volatile("mma.sync.aligned.m16n8k8.row.col.f32.tf32.tf32.f32 "
                 "{%0,%1,%2,%3}, {%4,%5,%6,%7}, {%8,%9}, {%0,%1,%2,%3};"
                 : "+f"(c0), "+f"(c1), "+f"(c2), "+f"(c3)
                 : "r"(a0), "r"(a1), "r"(a2), "r"(a3), "r"(b0), "r"(b1));
}

__global__ void __launch_bounds__(128)
attn_flash_tf32(const float* __restrict__ Q, const float* __restrict__ K,
                const float* __restrict__ V, const int* __restrict__ VL,
                float* __restrict__ O)
{
    __shared__ uint32_t sK[BN * LDK];   // K tile; also Q staging; also per-warp P region
    __shared__ uint32_t sV[BN * LDV];   // V tile

    const int tid  = threadIdx.x;
    const int warp = tid >> 5;
    const int lane = tid & 31;
    const int g    = lane >> 2;   // group id (row within m8)
    const int t    = lane & 3;    // thread-in-group
    const int batch = blockIdx.y;
    const int q0    = blockIdx.x * BM;
    const int valid = VL[batch];

    const float* Qb = Q + ((size_t)batch * SEQ + q0) * HD;
    const float* Kb = K + (size_t)batch * SEQ * HD;
    const float* Vb = V + (size_t)batch * SEQ * HD;

    // ---- stage Q tile into sK (scaled by 1/sqrt(d)=0.125, tf32-rounded) ----
    #pragma unroll
    for (int i = 0; i < 8; i++) {
        int vi  = i * 128 + tid;       // float4 index among 64*64/4=1024
        int row = vi >> 4;
        int col = (vi & 15) * 4;
        float4 v = *(const float4*)(Qb + row * HD + col);
        uint32_t* dst = &sK[row * LDK + col];
        dst[0] = f2tf32(v.x * 0.125f);
        dst[1] = f2tf32(v.y * 0.125f);
        dst[2] = f2tf32(v.z * 0.125f);
        dst[3] = f2tf32(v.w * 0.125f);
    }
    __syncthreads();

    // ---- Q fragments (row.col m16n8k8: A row = g / g+8, col = t / t+4 within each k8) ----
    uint32_t qa[8][4];
    {
        const int r0 = warp * 16 + g;
        #pragma unroll
        for (int k = 0; k < 8; k++) {
            const int c = k * 8 + t;
            qa[k][0] = sK[r0 * LDK + c];
            qa[k][1] = sK[(r0 + 8) * LDK + c];
            qa[k][2] = sK[r0 * LDK + c + 4];
            qa[k][3] = sK[(r0 + 8) * LDK + c + 4];
        }
    }

    float o[8][4];
    #pragma unroll
    for (int n = 0; n < 8; n++) { o[n][0]=0.f; o[n][1]=0.f; o[n][2]=0.f; o[n][3]=0.f; }
    float m0 = -INFINITY, m1 = -INFINITY, l0 = 0.f, l1 = 0.f;

    const int nkt = (valid + BN - 1) / BN;   // masked tiles contribute exactly 0 -> skip them
    for (int kt = 0; kt < nkt; kt++) {
        __syncthreads();  // prior-tile consumers (incl. P reads, V reads, Q-frag reads) done
        const float* Kt = Kb + (size_t)kt * BN * HD;
        const float* Vt = Vb + (size_t)kt * BN * HD;
        #pragma unroll
        for (int i = 0; i < 8; i++) {
            int vi  = i * 128 + tid;
            int row = vi >> 4;
            int col = (vi & 15) * 4;
            float4 kv = *(const float4*)(Kt + row * HD + col);
            float4 vv = *(const float4*)(Vt + row * HD + col);
            uint32_t* dk = &sK[row * LDK + col];
            dk[0]=f2tf32(kv.x); dk[1]=f2tf32(kv.y); dk[2]=f2tf32(kv.z); dk[3]=f2tf32(kv.w);
            uint32_t* dv = &sV[row * LDV + col];
            dv[0]=f2tf32(vv.x); dv[1]=f2tf32(vv.y); dv[2]=f2tf32(vv.z); dv[3]=f2tf32(vv.w);
        }
        __syncthreads();

        // ---- S = (Q/8) @ K^T : B frag b0 = K[key=n*8+g][dim=k*8+t], b1 = dim+4 ----
        float s[8][4];
        #pragma unroll
        for (int n = 0; n < 8; n++) {
            s[n][0]=0.f; s[n][1]=0.f; s[n][2]=0.f; s[n][3]=0.f;
            const uint32_t* krow = &sK[(n * 8 + g) * LDK];
            #pragma unroll
            for (int k = 0; k < 8; k++) {
                uint32_t b0 = krow[k * 8 + t];
                uint32_t b1 = krow[k * 8 + t + 4];
                mma_tf32(s[n][0], s[n][1], s[n][2], s[n][3],
                         qa[k][0], qa[k][1], qa[k][2], qa[k][3], b0, b1);
            }
        }

        // ---- mask columns >= valid ----
        const int kbase = kt * BN;
        #pragma unroll
        for (int n = 0; n < 8; n++) {
            int c = kbase + n * 8 + 2 * t;
            if (c     >= valid) { s[n][0] = -1e30f; s[n][2] = -1e30f; }
            if (c + 1 >= valid) { s[n][1] = -1e30f; s[n][3] = -1e30f; }
        }

        // ---- online softmax ----
        float tm0 = -INFINITY, tm1 = -INFINITY;
        #pragma unroll
        for (int n = 0; n < 8; n++) {
            tm0 = fmaxf(tm0, fmaxf(s[n][0], s[n][1]));
            tm1 = fmaxf(tm1, fmaxf(s[n][2], s[n][3]));
        }
        tm0 = fmaxf(tm0, __shfl_xor_sync(0xffffffffu, tm0, 1));
        tm0 = fmaxf(tm0, __shfl_xor_sync(0xffffffffu, tm0, 2));
        tm1 = fmaxf(tm1, __shfl_xor_sync(0xffffffffu, tm1, 1));
        tm1 = fmaxf(tm1, __shfl_xor_sync(0xffffffffu, tm1, 2));

        const float nm0 = fmaxf(m0, tm0);
        const float nm1 = fmaxf(m1, tm1);
        const float corr0 = __expf(m0 - nm0);
        const float corr1 = __expf(m1 - nm1);

        float rs0 = 0.f, rs1 = 0.f;
        #pragma unroll
        for (int n = 0; n < 8; n++) {
            s[n][0] = __expf(s[n][0] - nm0);
            s[n][1] = __expf(s[n][1] - nm0);
            s[n][2] = __expf(s[n][2] - nm1);
            s[n][3] = __expf(s[n][3] - nm1);
            rs0 += s[n][0] + s[n][1];
            rs1 += s[n][2] + s[n][3];
        }
        rs0 += __shfl_xor_sync(0xffffffffu, rs0, 1);
        rs0 += __shfl_xor_sync(0xffffffffu, rs0, 2);
        rs1 += __shfl_xor_sync(0xffffffffu, rs1, 1);
        rs1 += __shfl_xor_sync(0xffffffffu, rs1, 2);

        l0 = l0 * corr0 + rs0;
        l1 = l1 * corr1 + rs1;
        m0 = nm0; m1 = nm1;

        // ---- write P into sK's per-warp region (K fully consumed by all warps first) ----
        __syncthreads();
        {
            uint32_t* P = &sK[warp * 16 * LDK];
            #pragma unroll
            for (int n = 0; n < 8; n++) {
                int c = n * 8 + 2 * t;
                P[g * LDK + c]           = f2tf32(s[n][0]);
                P[g * LDK + c + 1]       = f2tf32(s[n][1]);
                P[(g + 8) * LDK + c]     = f2tf32(s[n][2]);
                P[(g + 8) * LDK + c + 1] = f2tf32(s[n][3]);
            }
        }
        __syncwarp();

        // ---- rescale O then O += P @ V ----
        #pragma unroll
        for (int n = 0; n < 8; n++) {
            o[n][0] *= corr0; o[n][1] *= corr0;
            o[n][2] *= corr1; o[n][3] *= corr1;
        }
        {
            const uint32_t* P = &sK[warp * 16 * LDK];
            #pragma unroll
            for (int k = 0; k < 8; k++) {
                uint32_t a0 = P[g * LDK + k * 8 + t];
                uint32_t a1 = P[(g + 8) * LDK + k * 8 + t];
                uint32_t a2 = P[g * LDK + k * 8 + t + 4];
                uint32_t a3 = P[(g + 8) * LDK + k * 8 + t + 4];
                #pragma unroll
                for (int n = 0; n < 8; n++) {
                    // B frag: b0 = V[key=k*8+t][dim=n*8+g], b1 = key+4
                    uint32_t b0 = sV[(k * 8 + t) * LDV + n * 8 + g];
                    uint32_t b1 = sV[(k * 8 + t + 4) * LDV + n * 8 + g];
                    mma_tf32(o[n][0], o[n][1], o[n][2], o[n][3],
                             a0, a1, a2, a3, b0, b1);
                }
            }
        }
    }

    // ---- epilogue: O /= l, write out ----
    const float inv0 = 1.f / l0;
    const float inv1 = 1.f / l1;
    const int row0 = q0 + warp * 16 + g;
    float* Ob = O + (size_t)batch * SEQ * HD;
    #pragma unroll
    for (int n = 0; n < 8; n++) {
        int col = n * 8 + 2 * t;
        float2 w0; w0.x = o[n][0] * inv0; w0.y = o[n][1] * inv0;
        float2 w1; w1.x = o[n][2] * inv1; w1.y = o[n][3] * inv1;
        *(float2*)(Ob + (size_t)row0 * HD + col)       = w0;
        *(float2*)(Ob + (size_t)(row0 + 8) * HD + col) = w1;
    }
}

extern "C" void kernel_launch(void* const* d_in, const int* in_sizes, int n_in,
                              void* d_out, int out_size) {
    const float* Q  = (const float*)d_in[0];
    const float* K  = (const float*)d_in[1];
    const float* V  = (const float*)d_in[2];
    const int*   VL = (const int*)d_in[3];
    float* O = (float*)d_out;

    dim3 grid(SEQ / BM, NB);   // (32 q-tiles, 32 batches)
    attn_flash_tf32<<<grid, 128>>>(Q, K, V, VL, O);
}

// round 3
// speedup vs baseline: 2.0551x; 2.0551x over previous
#include <cuda_runtime.h>
#include <cuda_fp16.h>
#include <cstdint>
#include <math.h>

// Problem shape (fixed for this dataset entry)
#define NB   32
#define SEQ  2048
#define HD   64

#define BM 64          // Q rows per CTA
#define BN 64          // keys per tile
#define LDQ 68         // Q staging stride (floats)
#define LDV 72         // V smem stride in halves (144B rows -> conflict-free ldmatrix)

// K fragment-major smem: [n-block 0..7][lane 0..31][16 values + 4 pad] (tf32 bits)
// value at slot (n, lane=g*4+t, k*2+h) = K[key=n*8+g][dim=k*8+t+4h]
#define KF_LANE_STRIDE 20
#define KF_SIZE (8 * 32 * KF_LANE_STRIDE)   // 5120 u32 = 20KB (>= 64*LDQ=4352 for Q staging)

__device__ __forceinline__ uint32_t f2tf32(float f) {
    uint32_t u;
    asm("cvt.rna.tf32.f32 %0, %1;" : "=r"(u) : "f"(f));
    return u;
}

__device__ __forceinline__ uint32_t packh2(float lo, float hi) {
    uint32_t u;
    asm("cvt.rn.f16x2.f32 %0, %1, %2;" : "=r"(u) : "f"(hi), "f"(lo));
    return u;
}

__device__ __forceinline__ void mma_tf32(float& c0, float& c1, float& c2, float& c3,
                                         uint32_t a0, uint32_t a1, uint32_t a2, uint32_t a3,
                                         uint32_t b0, uint32_t b1) {
    asm volatile("mma.sync.aligned.m16n8k8.row.col.f32.tf32.tf32.f32 "
                 "{%0,%1,%2,%3}, {%4,%5,%6,%7}, {%8,%9}, {%0,%1,%2,%3};"
                 : "+f"(c0), "+f"(c1), "+f"(c2), "+f"(c3)
                 : "r"(a0), "r"(a1), "r"(a2), "r"(a3), "r"(b0), "r"(b1));
}

__device__ __forceinline__ void mma_f16(float& c0, float& c1, float& c2, float& c3,
                                        uint32_t a0, uint32_t a1, uint32_t a2, uint32_t a3,
                                        uint32_t b0, uint32_t b1) {
    asm volatile("mma.sync.aligned.m16n8k16.row.col.f32.f16.f16.f32 "
                 "{%0,%1,%2,%3}, {%4,%5,%6,%7}, {%8,%9}, {%0,%1,%2,%3};"
                 : "+f"(c0), "+f"(c1), "+f"(c2), "+f"(c3)
                 : "r"(a0), "r"(a1), "r"(a2), "r"(a3), "r"(b0), "r"(b1));
}

__device__ __forceinline__ void ldmx4t(uint32_t& r0, uint32_t& r1, uint32_t& r2, uint32_t& r3,
                                       uint32_t saddr) {
    asm volatile("ldmatrix.sync.aligned.m8n8.x4.trans.shared.b16 {%0,%1,%2,%3}, [%4];"
                 : "=r"(r0), "=r"(r1), "=r"(r2), "=r"(r3) : "r"(saddr));
}

__global__ void __launch_bounds__(128)
attn_flash_v2(const float* __restrict__ Q, const float* __restrict__ K,
              const float* __restrict__ V, const int* __restrict__ VL,
              float* __restrict__ O)
{
    __shared__ alignas(16) uint32_t sKf[KF_SIZE];   // K fragments; also Q staging
    __shared__ alignas(16) __half   sV[BN * LDV];   // V tile fp16, [key][dim] padded

    const int tid  = threadIdx.x;
    const int warp = tid >> 5;
    const int lane = tid & 31;
    const int g    = lane >> 2;
    const int t    = lane & 3;
    const int batch = blockIdx.y;
    const int q0    = blockIdx.x * BM;
    const int valid = VL[batch];

    const float* Qb = Q + ((size_t)batch * SEQ + q0) * HD;
    const float* Kb = K + (size_t)batch * SEQ * HD;
    const float* Vb = V + (size_t)batch * SEQ * HD;

    // ---- stage Q tile (scaled by 1/8, tf32) into sKf used as a linear buffer ----
    #pragma unroll
    for (int i = 0; i < 8; i++) {
        int vi  = i * 128 + tid;
        int row = vi >> 4;
        int col = (vi & 15) * 4;
        float4 v = *(const float4*)(Qb + row * HD + col);
        uint32_t* dst = &sKf[row * LDQ + col];
        dst[0] = f2tf32(v.x * 0.125f);
        dst[1] = f2tf32(v.y * 0.125f);
        dst[2] = f2tf32(v.z * 0.125f);
        dst[3] = f2tf32(v.w * 0.125f);
    }
    __syncthreads();

    // ---- Q A-fragments (m16n8k8 row-major) ----
    uint32_t qa[8][4];
    {
        const int r0 = warp * 16 + g;
        #pragma unroll
        for (int k = 0; k < 8; k++) {
            const int c = k * 8 + t;
            qa[k][0] = sKf[r0 * LDQ + c];
            qa[k][1] = sKf[(r0 + 8) * LDQ + c];
            qa[k][2] = sKf[r0 * LDQ + c + 4];
            qa[k][3] = sKf[(r0 + 8) * LDQ + c + 4];
        }
    }

    float o[8][4];
    #pragma unroll
    for (int n = 0; n < 8; n++) { o[n][0]=0.f; o[n][1]=0.f; o[n][2]=0.f; o[n][3]=0.f; }
    float m0 = -INFINITY, m1 = -INFINITY, l0 = 0.f, l1 = 0.f;

    // per-lane ldmatrix address components
    const uint32_t sV_base = (uint32_t)__cvta_generic_to_shared(sV);
    const int ld_keyoff = ((lane >> 3) & 1) * 8 + (lane & 7);
    const int ld_dimoff = (lane >> 4) * 8;
    const uint32_t ld_lane_base = sV_base + (uint32_t)(ld_keyoff * LDV + ld_dimoff) * 2u;

    const int nkt = (valid + BN - 1) / BN;   // fully masked tiles contribute exactly 0
    for (int kt = 0; kt < nkt; kt++) {
        __syncthreads();  // all consumers of previous sKf/sV done
        const float* Kt = Kb + (size_t)kt * BN * HD;
        const float* Vt = Vb + (size_t)kt * BN * HD;
        #pragma unroll
        for (int i = 0; i < 8; i++) {
            int vi  = i * 128 + tid;
            int row = vi >> 4;
            int col = (vi & 15) * 4;
            float4 kv = *(const float4*)(Kt + row * HD + col);
            float4 vv = *(const float4*)(Vt + row * HD + col);
            // K scatter to fragment-major layout (conflict-free)
            int n = row >> 3, gg = row & 7, k = col >> 3, h = (col >> 2) & 1;
            uint32_t base = (uint32_t)((n * 32 + gg * 4) * KF_LANE_STRIDE + k * 2 + h);
            sKf[base]                      = f2tf32(kv.x);
            sKf[base + KF_LANE_STRIDE]     = f2tf32(kv.y);
            sKf[base + 2*KF_LANE_STRIDE]   = f2tf32(kv.z);
            sKf[base + 3*KF_LANE_STRIDE]   = f2tf32(kv.w);
            // V as fp16, [key][dim]
            uint2 pv;
            pv.x = packh2(vv.x, vv.y);
            pv.y = packh2(vv.z, vv.w);
            *reinterpret_cast<uint2*>(&sV[row * LDV + col]) = pv;
        }
        __syncthreads();

        // ---- S = (Q/8) @ K^T : B-frags via vectorized LDS.128 from fragment-major K ----
        float s[8][4];
        {
            const uint32_t* kf = &sKf[lane * KF_LANE_STRIDE];
            #pragma unroll
            for (int n = 0; n < 8; n++) {
                s[n][0]=0.f; s[n][1]=0.f; s[n][2]=0.f; s[n][3]=0.f;
                const uint4* p = (const uint4*)(kf + n * 32 * KF_LANE_STRIDE);
                uint4 w0 = p[0], w1 = p[1], w2 = p[2], w3 = p[3];
                mma_tf32(s[n][0],s[n][1],s[n][2],s[n][3], qa[0][0],qa[0][1],qa[0][2],qa[0][3], w0.x, w0.y);
                mma_tf32(s[n][0],s[n][1],s[n][2],s[n][3], qa[1][0],qa[1][1],qa[1][2],qa[1][3], w0.z, w0.w);
                mma_tf32(s[n][0],s[n][1],s[n][2],s[n][3], qa[2][0],qa[2][1],qa[2][2],qa[2][3], w1.x, w1.y);
                mma_tf32(s[n][0],s[n][1],s[n][2],s[n][3], qa[3][0],qa[3][1],qa[3][2],qa[3][3], w1.z, w1.w);
                mma_tf32(s[n][0],s[n][1],s[n][2],s[n][3], qa[4][0],qa[4][1],qa[4][2],qa[4][3], w2.x, w2.y);
                mma_tf32(s[n][0],s[n][1],s[n][2],s[n][3], qa[5][0],qa[5][1],qa[5][2],qa[5][3], w2.z, w2.w);
                mma_tf32(s[n][0],s[n][1],s[n][2],s[n][3], qa[6][0],qa[6][1],qa[6][2],qa[6][3], w3.x, w3.y);
                mma_tf32(s[n][0],s[n][1],s[n][2],s[n][3], qa[7][0],qa[7][1],qa[7][2],qa[7][3], w3.z, w3.w);
            }
        }

        // ---- mask columns >= valid ----
        const int kbase = kt * BN;
        #pragma unroll
        for (int n = 0; n < 8; n++) {
            int c = kbase + n * 8 + 2 * t;
            if (c     >= valid) { s[n][0] = -1e30f; s[n][2] = -1e30f; }
            if (c + 1 >= valid) { s[n][1] = -1e30f; s[n][3] = -1e30f; }
        }

        // ---- online softmax ----
        float tm0 = -INFINITY, tm1 = -INFINITY;
        #pragma unroll
        for (int n = 0; n < 8; n++) {
            tm0 = fmaxf(tm0, fmaxf(s[n][0], s[n][1]));
            tm1 = fmaxf(tm1, fmaxf(s[n][2], s[n][3]));
        }
        tm0 = fmaxf(tm0, __shfl_xor_sync(0xffffffffu, tm0, 1));
        tm0 = fmaxf(tm0, __shfl_xor_sync(0xffffffffu, tm0, 2));
        tm1 = fmaxf(tm1, __shfl_xor_sync(0xffffffffu, tm1, 1));
        tm1 = fmaxf(tm1, __shfl_xor_sync(0xffffffffu, tm1, 2));

        const float nm0 = fmaxf(m0, tm0);
        const float nm1 = fmaxf(m1, tm1);
        const float corr0 = __expf(m0 - nm0);
        const float corr1 = __expf(m1 - nm1);

        float rs0 = 0.f, rs1 = 0.f;
        #pragma unroll
        for (int n = 0; n < 8; n++) {
            s[n][0] = __expf(s[n][0] - nm0);
            s[n][1] = __expf(s[n][1] - nm0);
            s[n][2] = __expf(s[n][2] - nm1);
            s[n][3] = __expf(s[n][3] - nm1);
            rs0 += s[n][0] + s[n][1];
            rs1 += s[n][2] + s[n][3];
        }
        rs0 += __shfl_xor_sync(0xffffffffu, rs0, 1);
        rs0 += __shfl_xor_sync(0xffffffffu, rs0, 2);
        rs1 += __shfl_xor_sync(0xffffffffu, rs1, 1);
        rs1 += __shfl_xor_sync(0xffffffffu, rs1, 2);

        l0 = l0 * corr0 + rs0;
        l1 = l1 * corr1 + rs1;
        m0 = nm0; m1 = nm1;

        // ---- rescale O, then O += P @ V  (P packed in registers, fp16 k16 MMA) ----
        #pragma unroll
        for (int n = 0; n < 8; n++) {
            o[n][0] *= corr0; o[n][1] *= corr0;
            o[n][2] *= corr1; o[n][3] *= corr1;
        }
        #pragma unroll
        for (int j = 0; j < 4; j++) {           // key chunk of 16: keys 16j..16j+15
            uint32_t a0 = packh2(s[2*j][0],   s[2*j][1]);
            uint32_t a1 = packh2(s[2*j][2],   s[2*j][3]);
            uint32_t a2 = packh2(s[2*j+1][0], s[2*j+1][1]);
            uint32_t a3 = packh2(s[2*j+1][2], s[2*j+1][3]);
            uint32_t base_j = ld_lane_base + (uint32_t)(16 * j * LDV) * 2u;
            #pragma unroll
            for (int np = 0; np < 4; np++) {    // dim block pair (n = 2np, 2np+1)
                uint32_t r0, r1, r2, r3;
                ldmx4t(r0, r1, r2, r3, base_j + (uint32_t)np * 32u);
                mma_f16(o[2*np][0],   o[2*np][1],   o[2*np][2],   o[2*np][3],   a0,a1,a2,a3, r0, r1);
                mma_f16(o[2*np+1][0], o[2*np+1][1], o[2*np+1][2], o[2*np+1][3], a0,a1,a2,a3, r2, r3);
            }
        }
    }

    // ---- epilogue ----
    const float inv0 = 1.f / l0;
    const float inv1 = 1.f / l1;
    const int row0 = q0 + warp * 16 + g;
    float* Ob = O + (size_t)batch * SEQ * HD;
    #pragma unroll
    for (int n = 0; n < 8; n++) {
        int col = n * 8 + 2 * t;
        float2 w0; w0.x = o[n][0] * inv0; w0.y = o[n][1] * inv0;
        float2 w1; w1.x = o[n][2] * inv1; w1.y = o[n][3] * inv1;
        *(float2*)(Ob + (size_t)row0 * HD + col)       = w0;
        *(float2*)(Ob + (size_t)(row0 + 8) * HD + col) = w1;
    }
}

extern "C" void kernel_launch(void* const* d_in, const int* in_sizes, int n_in,
                              void* d_out, int out_size) {
    const float* Q  = (const float*)d_in[0];
    const float* K  = (const float*)d_in[1];
    const float* V  = (const float*)d_in[2];
    const int*   VL = (const int*)d_in[3];
    float* O = (float*)d_out;

    dim3 grid(SEQ / BM, NB);   // (32 q-tiles, 32 batches)
    attn_flash_v2<<<grid, 128>>>(Q, K, V, VL, O);
}

// round 4
// speedup vs baseline: 2.7702x; 1.3480x over previous
#include <cuda_runtime.h>
#include <cuda_fp16.h>
#include <cstdint>
#include <math.h>

// Problem shape (fixed for this dataset entry)
#define NB   32
#define SEQ  2048
#define HD   64

#define BM 64          // Q rows per CTA
#define BN 64          // keys per tile
#define LDH 72         // smem stride in halves (144B rows -> conflict-free ldmatrix)

__device__ __forceinline__ uint32_t packh2(float lo, float hi) {
    uint32_t u;
    asm("cvt.rn.f16x2.f32 %0, %1, %2;" : "=r"(u) : "f"(hi), "f"(lo));
    return u;
}

__device__ __forceinline__ void mma_f16(float& c0, float& c1, float& c2, float& c3,
                                        uint32_t a0, uint32_t a1, uint32_t a2, uint32_t a3,
                                        uint32_t b0, uint32_t b1) {
    asm volatile("mma.sync.aligned.m16n8k16.row.col.f32.f16.f16.f32 "
                 "{%0,%1,%2,%3}, {%4,%5,%6,%7}, {%8,%9}, {%0,%1,%2,%3};"
                 : "+f"(c0), "+f"(c1), "+f"(c2), "+f"(c3)
                 : "r"(a0), "r"(a1), "r"(a2), "r"(a3), "r"(b0), "r"(b1));
}

__device__ __forceinline__ void ldmx4(uint32_t& r0, uint32_t& r1, uint32_t& r2, uint32_t& r3,
                                      uint32_t saddr) {
    asm volatile("ldmatrix.sync.aligned.m8n8.x4.shared.b16 {%0,%1,%2,%3}, [%4];"
                 : "=r"(r0), "=r"(r1), "=r"(r2), "=r"(r3) : "r"(saddr));
}

__device__ __forceinline__ void ldmx4t(uint32_t& r0, uint32_t& r1, uint32_t& r2, uint32_t& r3,
                                       uint32_t saddr) {
    asm volatile("ldmatrix.sync.aligned.m8n8.x4.trans.shared.b16 {%0,%1,%2,%3}, [%4];"
                 : "=r"(r0), "=r"(r1), "=r"(r2), "=r"(r3) : "r"(saddr));
}

__global__ void __launch_bounds__(128, 4)
attn_flash_v3(const float* __restrict__ Q, const float* __restrict__ K,
              const float* __restrict__ V, const int* __restrict__ VL,
              float* __restrict__ O)
{
    __shared__ alignas(16) __half sK[BN * LDH];   // K tile fp16 [key][dim]; also Q staging
    __shared__ alignas(16) __half sV[BN * LDH];   // V tile fp16 [key][dim]

    const int tid  = threadIdx.x;
    const int warp = tid >> 5;
    const int lane = tid & 31;
    const int g    = lane >> 2;
    const int t    = lane & 3;
    const int batch = blockIdx.y;
    const int q0    = blockIdx.x * BM;
    const int valid = VL[batch];

    const float* Qb = Q + ((size_t)batch * SEQ + q0) * HD;
    const float* Kb = K + (size_t)batch * SEQ * HD;
    const float* Vb = V + (size_t)batch * SEQ * HD;

    const uint32_t sK_base = (uint32_t)__cvta_generic_to_shared(sK);
    const uint32_t sV_base = (uint32_t)__cvta_generic_to_shared(sV);

    // ---- stage Q tile (scaled by 1/sqrt(64)=0.125) as fp16 into sK ----
    #pragma unroll
    for (int i = 0; i < 8; i++) {
        int vi  = i * 128 + tid;
        int row = vi >> 4;
        int col = (vi & 15) * 4;
        float4 v = *(const float4*)(Qb + row * HD + col);
        uint2 pv;
        pv.x = packh2(v.x * 0.125f, v.y * 0.125f);
        pv.y = packh2(v.z * 0.125f, v.w * 0.125f);
        *reinterpret_cast<uint2*>(&sK[row * LDH + col]) = pv;
    }
    __syncthreads();

    // ---- Q A-fragments (m16n8k16): 4 k-chunks of 16 dims ----
    // x4 tile order: (rowlo,dimlo),(rowhi,dimlo),(rowlo,dimhi),(rowhi,dimhi) -> a0..a3
    uint32_t qa[4][4];
    {
        const int q4   = lane >> 3;                    // tile group 0..3
        const int arow = warp * 16 + (q4 & 1) * 8 + (lane & 7);
        const int acol = (q4 >> 1) * 8;
        #pragma unroll
        for (int kc = 0; kc < 4; kc++) {
            uint32_t addr = sK_base + (uint32_t)(arow * LDH + kc * 16 + acol) * 2u;
            ldmx4(qa[kc][0], qa[kc][1], qa[kc][2], qa[kc][3], addr);
        }
    }

    float o[8][4];
    #pragma unroll
    for (int n = 0; n < 8; n++) { o[n][0]=0.f; o[n][1]=0.f; o[n][2]=0.f; o[n][3]=0.f; }
    float m0 = -INFINITY, m1 = -INFINITY, l0 = 0.f, l1 = 0.f;

    // per-lane ldmatrix address components
    const int q4 = lane >> 3;
    // K B-frag (non-trans): tile j: key = npair*16 + (j>>1)*8 + (lane&7), dim = kc*16 + (j&1)*8
    const int kb_keyoff = (q4 >> 1) * 8 + (lane & 7);
    const int kb_dimoff = (q4 & 1) * 8;
    // V B-frag (trans): tile j: key = 16j' base + (j&1)*8 + (lane&7), dim = (j>>1)*8
    const int vb_keyoff = (q4 & 1) * 8 + (lane & 7);
    const int vb_dimoff = (q4 >> 1) * 8;
    const uint32_t vb_lane_base = sV_base + (uint32_t)(vb_keyoff * LDH + vb_dimoff) * 2u;

    const int nkt = (valid + BN - 1) / BN;   // fully masked tiles contribute exactly 0
    for (int kt = 0; kt < nkt; kt++) {
        __syncthreads();  // all consumers of previous sK/sV done (incl. Q frags on kt==0)
        const float* Kt = Kb + (size_t)kt * BN * HD;
        const float* Vt = Vb + (size_t)kt * BN * HD;
        #pragma unroll
        for (int i = 0; i < 8; i++) {
            int vi  = i * 128 + tid;
            int row = vi >> 4;
            int col = (vi & 15) * 4;
            float4 kv = *(const float4*)(Kt + row * HD + col);
            float4 vv = *(const float4*)(Vt + row * HD + col);
            uint2 pk, pv;
            pk.x = packh2(kv.x, kv.y);
            pk.y = packh2(kv.z, kv.w);
            pv.x = packh2(vv.x, vv.y);
            pv.y = packh2(vv.z, vv.w);
            *reinterpret_cast<uint2*>(&sK[row * LDH + col]) = pk;
            *reinterpret_cast<uint2*>(&sV[row * LDH + col]) = pv;
        }
        __syncthreads();

        // ---- S = (Q/8) @ K^T : fp16 m16n8k16, B-frags via ldmatrix.x4 ----
        float s[8][4];
        #pragma unroll
        for (int n = 0; n < 8; n++) { s[n][0]=0.f; s[n][1]=0.f; s[n][2]=0.f; s[n][3]=0.f; }
        #pragma unroll
        for (int kc = 0; kc < 4; kc++) {
            #pragma unroll
            for (int npair = 0; npair < 4; npair++) {
                uint32_t addr = sK_base +
                    (uint32_t)((npair * 16 + kb_keyoff) * LDH + kc * 16 + kb_dimoff) * 2u;
                uint32_t r0, r1, r2, r3;
                ldmx4(r0, r1, r2, r3, addr);
                int n0 = npair * 2, n1 = npair * 2 + 1;
                mma_f16(s[n0][0], s[n0][1], s[n0][2], s[n0][3],
                        qa[kc][0], qa[kc][1], qa[kc][2], qa[kc][3], r0, r1);
                mma_f16(s[n1][0], s[n1][1], s[n1][2], s[n1][3],
                        qa[kc][0], qa[kc][1], qa[kc][2], qa[kc][3], r2, r3);
            }
        }

        // ---- mask columns >= valid ----
        const int kbase = kt * BN;
        #pragma unroll
        for (int n = 0; n < 8; n++) {
            int c = kbase + n * 8 + 2 * t;
            if (c     >= valid) { s[n][0] = -1e30f; s[n][2] = -1e30f; }
            if (c + 1 >= valid) { s[n][1] = -1e30f; s[n][3] = -1e30f; }
        }

        // ---- online softmax ----
        float tm0 = -INFINITY, tm1 = -INFINITY;
        #pragma unroll
        for (int n = 0; n < 8; n++) {
            tm0 = fmaxf(tm0, fmaxf(s[n][0], s[n][1]));
            tm1 = fmaxf(tm1, fmaxf(s[n][2], s[n][3]));
        }
        tm0 = fmaxf(tm0, __shfl_xor_sync(0xffffffffu, tm0, 1));
        tm0 = fmaxf(tm0, __shfl_xor_sync(0xffffffffu, tm0, 2));
        tm1 = fmaxf(tm1, __shfl_xor_sync(0xffffffffu, tm1, 1));
        tm1 = fmaxf(tm1, __shfl_xor_sync(0xffffffffu, tm1, 2));

        const float nm0 = fmaxf(m0, tm0);
        const float nm1 = fmaxf(m1, tm1);
        const float corr0 = __expf(m0 - nm0);
        const float corr1 = __expf(m1 - nm1);

        float rs0 = 0.f, rs1 = 0.f;
        #pragma unroll
        for (int n = 0; n < 8; n++) {
            s[n][0] = __expf(s[n][0] - nm0);
            s[n][1] = __expf(s[n][1] - nm0);
            s[n][2] = __expf(s[n][2] - nm1);
            s[n][3] = __expf(s[n][3] - nm1);
            rs0 += s[n][0] + s[n][1];
            rs1 += s[n][2] + s[n][3];
        }
        rs0 += __shfl_xor_sync(0xffffffffu, rs0, 1);
        rs0 += __shfl_xor_sync(0xffffffffu, rs0, 2);
        rs1 += __shfl_xor_sync(0xffffffffu, rs1, 1);
        rs1 += __shfl_xor_sync(0xffffffffu, rs1, 2);

        l0 = l0 * corr0 + rs0;
        l1 = l1 * corr1 + rs1;
        m0 = nm0; m1 = nm1;

        // ---- rescale O, then O += P @ V  (P packed in registers, fp16 k16 MMA) ----
        #pragma unroll
        for (int n = 0; n < 8; n++) {
            o[n][0] *= corr0; o[n][1] *= corr0;
            o[n][2] *= corr1; o[n][3] *= corr1;
        }
        #pragma unroll
        for (int j = 0; j < 4; j++) {           // key chunk of 16: keys 16j..16j+15
            uint32_t a0 = packh2(s[2*j][0],   s[2*j][1]);
            uint32_t a1 = packh2(s[2*j][2],   s[2*j][3]);
            uint32_t a2 = packh2(s[2*j+1][0], s[2*j+1][1]);
            uint32_t a3 = packh2(s[2*j+1][2], s[2*j+1][3]);
            uint32_t base_j = vb_lane_base + (uint32_t)(16 * j * LDH) * 2u;
            #pragma unroll
            for (int np = 0; np < 4; np++) {    // dim block pair (n = 2np, 2np+1)
                uint32_t r0, r1, r2, r3;
                ldmx4t(r0, r1, r2, r3, base_j + (uint32_t)np * 32u);
                mma_f16(o[2*np][0],   o[2*np][1],   o[2*np][2],   o[2*np][3],   a0,a1,a2,a3, r0, r1);
                mma_f16(o[2*np+1][0], o[2*np+1][1], o[2*np+1][2], o[2*np+1][3], a0,a1,a2,a3, r2, r3);
            }
        }
    }

    // ---- epilogue ----
    const float inv0 = 1.f / l0;
    const float inv1 = 1.f / l1;
    const int row0 = q0 + warp * 16 + g;
    float* Ob = O + (size_t)batch * SEQ * HD;
    #pragma unroll
    for (int n = 0; n < 8; n++) {
        int col = n * 8 + 2 * t;
        float2 w0; w0.x = o[n][0] * inv0; w0.y = o[n][1] * inv0;
        float2 w1; w1.x = o[n][2] * inv1; w1.y = o[n][3] * inv1;
        *(float2*)(Ob + (size_t)row0 * HD + col)       = w0;
        *(float2*)(Ob + (size_t)(row0 + 8) * HD + col) = w1;
    }
}

extern "C" void kernel_launch(void* const* d_in, const int* in_sizes, int n_in,
                              void* d_out, int out_size) {
    const float* Q  = (const float*)d_in[0];
    const float* K  = (const float*)d_in[1];
    const float* V  = (const float*)d_in[2];
    const int*   VL = (const int*)d_in[3];
    float* O = (float*)d_out;

    dim3 grid(SEQ / BM, NB);   // (32 q-tiles, 32 batches)
    attn_flash_v3<<<grid, 128>>>(Q, K, V, VL, O);
}